// round 7
// baseline (speedup 1.0000x reference)
#include <cuda_runtime.h>
#include <math.h>

// Problem shape (fixed by reference setup_inputs)
#define BATCH 2048
#define NLABELS 50000
#define NTRIALS 64

// One thread per (row, trial<8): probe 8 trials/row in ONE parallel wave.
// P(row unresolved after 8 trials) ~ 0.24^8 ~ 1e-5; fallback loop keeps
// exactness for arbitrary inputs.
#define TRIALS_PROBE 8
#define ROWS_PER_WARP 4                           // 32 / 8
#define WARPS_PER_BLOCK 8
#define THREADS_PER_BLOCK (WARPS_PER_BLOCK * 32)  // 256
#define ROWS_PER_BLOCK (WARPS_PER_BLOCK * ROWS_PER_WARP)  // 32
#define NUM_BLOCKS (BATCH / ROWS_PER_BLOCK)       // 64

// Scratch partials (no allocations allowed anywhere).
__device__ float g_partials[NUM_BLOCKS];

__global__ void __launch_bounds__(THREADS_PER_BLOCK)
warp_loss_main(const float* __restrict__ inp,
               const int* __restrict__ pos_idx,
               const int* __restrict__ neg_cands)
{
    const int tid       = threadIdx.x;
    const int lane      = tid & 31;
    const int wid       = tid >> 5;
    const int row_local = lane >> 3;              // 0..3 : row within warp
    const int sub       = lane & 7;               // 0..7 : trial within probe
    const int row       = (blockIdx.x * WARPS_PER_BLOCK + wid) * ROWS_PER_WARP
                          + row_local;

    const long  base  = (long)row * NLABELS;
    // Independent loads issued back-to-back (2-deep chains, fully overlapped):
    const int   p     = __ldg(pos_idx + row);
    const int   idx0  = __ldg(neg_cands + row * NTRIALS + sub);
    const float pos_s = __ldg(inp + base + p);            // 1 line / row
    const float neg0  = __ldg(inp + base + idx0);         // random gather
    const float thr   = pos_s - 1.0f;                     // margin>=0 <=> neg>=thr

    // ---- round 0: trials 0..7 fully parallel ----
    const unsigned acc = __ballot_sync(0xffffffffu, neg0 >= thr);
    const unsigned oct = (acc >> (row_local * 8)) & 0xFFu;

    float loss     = 0.0f;
    bool  resolved = (oct != 0u);
    {
        const int   fin = oct ? (__ffs(oct) - 1) : 0;
        const float sel = __shfl_sync(0xffffffffu, neg0, row_local * 8 + fin);
        if (resolved && sub == 0) {
            const float nt = (float)(fin + 1);
            const float L  = logf(floorf((float)(NLABELS - 1) / nt));
            loss = L * (1.0f - pos_s + sel);
        }
    }

    // ---- fallback (prob ~1e-5 per row): trials 8..63 in chunks of 8 ----
    if (!__all_sync(0xffffffffu, resolved)) {
        #pragma unroll 1
        for (int k = 1; k < NTRIALS / TRIALS_PROBE; k++) {
            const int trial = k * TRIALS_PROBE + sub;
            float neg = 0.0f;
            bool  okv = false;
            if (!resolved) {
                const int idx = __ldg(neg_cands + row * NTRIALS + trial);
                neg = __ldg(inp + base + idx);
                okv = (neg >= thr);
            }
            const unsigned a  = __ballot_sync(0xffffffffu, okv);
            const unsigned o8 = (a >> (row_local * 8)) & 0xFFu;
            const int   fin = o8 ? (__ffs(o8) - 1) : 0;
            const float sel = __shfl_sync(0xffffffffu, neg, row_local * 8 + fin);
            if (!resolved && o8) {
                if (sub == 0) {
                    const int   first = k * TRIALS_PROBE + fin;
                    const float nt    = (float)(first + 1);
                    const float L     = logf(floorf((float)(NLABELS - 1) / nt));
                    loss = L * (1.0f - pos_s + sel);
                }
                resolved = true;
            }
            if (__all_sync(0xffffffffu, resolved)) break;
        }
    }
    // Never-resolved rows contribute 0 (matches reference when !any_ok).

    // ---- deterministic warp reduce -> block partial (no atomics, no fence) ----
    #pragma unroll
    for (int off = 16; off >= 1; off >>= 1)
        loss += __shfl_xor_sync(0xffffffffu, loss, off);

    __shared__ float s_warp[WARPS_PER_BLOCK];
    if (lane == 0) s_warp[wid] = loss;
    __syncthreads();
    if (tid == 0) {
        float sum = 0.0f;
        #pragma unroll
        for (int i = 0; i < WARPS_PER_BLOCK; i++) sum += s_warp[i];
        g_partials[blockIdx.x] = sum;
    }
}

// Tiny second graph node: one warp sums the 64 partials (L2-hot), fixed order.
__global__ void __launch_bounds__(32)
warp_loss_reduce(float* __restrict__ out)
{
    const int lane = threadIdx.x;
    float v = g_partials[lane] + g_partials[lane + 32];
    #pragma unroll
    for (int off = 16; off >= 1; off >>= 1)
        v += __shfl_xor_sync(0xffffffffu, v, off);
    if (lane == 0) out[0] = v;
}

extern "C" void kernel_launch(void* const* d_in, const int* in_sizes, int n_in,
                              void* d_out, int out_size)
{
    // metadata order: input (f32 [B,Y]), target (i32, UNUSED), pos_idx (i32 [B]),
    //                 neg_cands (i32 [B,T]); output f32 [1]
    const float* inp     = (const float*)d_in[0];
    const int*   pos_idx = (const int*)d_in[2];
    const int*   neg     = (const int*)d_in[3];
    float*       out     = (float*)d_out;

    warp_loss_main<<<NUM_BLOCKS, THREADS_PER_BLOCK>>>(inp, pos_idx, neg);
    warp_loss_reduce<<<1, 32>>>(out);
}

// round 8
// speedup vs baseline: 1.2305x; 1.2305x over previous
#include <cuda_runtime.h>
#include <math.h>

// Problem shape (fixed by reference setup_inputs)
#define BATCH 2048
#define NLABELS 50000
#define NTRIALS 64

// One warp per row; lane = trial. One ballot resolves trials 0..31.
// P(row unresolved after 32 trials) ~ 0.24^32 ~ 1e-20 on this data;
// the guarded fallback over trials 32..63 keeps exactness for ANY input.
#define WARPS_PER_BLOCK 8
#define THREADS_PER_BLOCK (WARPS_PER_BLOCK * 32)   // 256
#define NUM_BLOCKS (BATCH / WARPS_PER_BLOCK)       // 256  (empirically best shape)

// Scratch partials (no allocations allowed anywhere).
__device__ float g_partials[NUM_BLOCKS];

__global__ void __launch_bounds__(THREADS_PER_BLOCK)
warp_loss_main(const float* __restrict__ inp,
               const int* __restrict__ pos_idx,
               const int* __restrict__ neg_cands)
{
    const int lane = threadIdx.x & 31;
    const int wid  = threadIdx.x >> 5;
    const int row  = blockIdx.x * WARPS_PER_BLOCK + wid;

    const long  base  = (long)row * NLABELS;
    // Independent 2-deep chains, all issued up front:
    const int   p     = __ldg(pos_idx + row);                   // broadcast
    const int   idx0  = __ldg(neg_cands + row * NTRIALS + lane); // coalesced
    const float pos_s = __ldg(inp + base + p);                  // 1 line/row
    const float neg0  = __ldg(inp + base + idx0);               // random gather
    const float thr   = pos_s - 1.0f;              // margin>=0 <=> neg>=thr

    // ---- trials 0..31: one ballot ----
    const unsigned m0 = __ballot_sync(0xffffffffu, neg0 >= thr);

    float loss = 0.0f;
    if (m0) {
        const int   first = __ffs(m0) - 1;
        const float sel   = __shfl_sync(0xffffffffu, neg0, first);
        if (lane == 0) {
            const float nt = (float)(first + 1);
            const float L  = logf(floorf((float)(NLABELS - 1) / nt));
            loss = L * (1.0f - pos_s + sel);
        }
    } else {
        // ---- fallback: trials 32..63 (statistically never taken) ----
        const int   idx1 = __ldg(neg_cands + row * NTRIALS + 32 + lane);
        const float neg1 = __ldg(inp + base + idx1);
        const unsigned m1 = __ballot_sync(0xffffffffu, neg1 >= thr);
        if (m1) {
            const int   f   = __ffs(m1) - 1;
            const float sel = __shfl_sync(0xffffffffu, neg1, f);
            if (lane == 0) {
                const float nt = (float)(32 + f + 1);
                const float L  = logf(floorf((float)(NLABELS - 1) / nt));
                loss = L * (1.0f - pos_s + sel);
            }
        }
        // else: no accepted negative -> loss stays 0 (matches reference).
    }

    // ---- block partial: lane 0 of each warp holds the row loss ----
    __shared__ float s_warp[WARPS_PER_BLOCK];
    if (lane == 0) s_warp[wid] = loss;
    __syncthreads();
    if (threadIdx.x == 0) {
        float sum = 0.0f;
        #pragma unroll
        for (int i = 0; i < WARPS_PER_BLOCK; i++) sum += s_warp[i];
        g_partials[blockIdx.x] = sum;
    }
}

// Tiny second graph node: one warp sums 256 partials (L2-hot), fixed order.
__global__ void __launch_bounds__(32)
warp_loss_reduce(float* __restrict__ out)
{
    const int lane = threadIdx.x;
    float v = 0.0f;
    #pragma unroll
    for (int j = 0; j < NUM_BLOCKS / 32; j++)
        v += g_partials[lane + j * 32];
    #pragma unroll
    for (int off = 16; off >= 1; off >>= 1)
        v += __shfl_xor_sync(0xffffffffu, v, off);
    if (lane == 0) out[0] = v;
}

extern "C" void kernel_launch(void* const* d_in, const int* in_sizes, int n_in,
                              void* d_out, int out_size)
{
    // metadata order: input (f32 [B,Y]), target (i32, UNUSED), pos_idx (i32 [B]),
    //                 neg_cands (i32 [B,T]); output f32 [1]
    const float* inp     = (const float*)d_in[0];
    const int*   pos_idx = (const int*)d_in[2];
    const int*   neg     = (const int*)d_in[3];
    float*       out     = (float*)d_out;

    warp_loss_main<<<NUM_BLOCKS, THREADS_PER_BLOCK>>>(inp, pos_idx, neg);
    warp_loss_reduce<<<1, 32>>>(out);
}